// round 4
// baseline (speedup 1.0000x reference)
#include <cuda_runtime.h>
#include <math.h>

// ---------------------------------------------------------------------------
// Problem constants
// ---------------------------------------------------------------------------
#define T_SEQ 1024
#define DMODEL 1024
#define NHEAD 16           // distinct K heads
#define HTOT 64            // total Q/V heads (4 branches x 16)
#define DH 64
#define SIG_SCALE 1.8137993642342178f   // pi / sqrt(3)
#define ATTN_SCALE 0.125f               // DH^-0.5

// ---------------------------------------------------------------------------
// Device scratch (no allocations allowed -> __device__ globals)
// ---------------------------------------------------------------------------
__device__ float g_Q[T_SEQ * HTOT * DH];      // [t][h][d]  t*4096 + h*64 + d
__device__ float g_K[T_SEQ * NHEAD * DH];     // [t][kh][d] t*1024 + kh*64 + d
__device__ float g_V[T_SEQ * HTOT * DH];      // [t][h][d]
__device__ float g_dnm[NHEAD * T_SEQ];        // kh*1024 + t : sqrt(max(sum k^2,1e-6))
__device__ float g_cos[T_SEQ * 32];
__device__ float g_sin[T_SEQ * 32];
__device__ float g_ctxh[HTOT * T_SEQ * DH];   // h*65536 + t*64 + d

// ---------------------------------------------------------------------------
// RoPE cos/sin table (double precision for accuracy, tiny cost)
// ---------------------------------------------------------------------------
__global__ void rope_table_kernel() {
    int idx = blockIdx.x * blockDim.x + threadIdx.x;
    if (idx >= T_SEQ * 32) return;
    int t = idx >> 5;
    int i = idx & 31;
    double inv = pow(10000.0, -2.0 * (double)i / 64.0);
    double a = (double)t * inv;
    g_cos[idx] = (float)cos(a);
    g_sin[idx] = (float)sin(a);
}

// ---------------------------------------------------------------------------
// In-place RoPE. One warp per (t, head) row of 64 floats.
// x1 = x[0::2], x2 = x[1::2]; out = [x1*c - x2*s | x1*s + x2*c]
// which == 0 : Q buffer (HTOT heads)
// which == 1 : K buffer (NHEAD heads) + per-key denom (norm is rotation-inv.)
// ---------------------------------------------------------------------------
__global__ void rope_apply_kernel(int which) {
    int warp = (blockIdx.x * blockDim.x + threadIdx.x) >> 5;
    int lane = threadIdx.x & 31;
    int nheads = (which == 0) ? HTOT : NHEAD;
    float* buf = (which == 0) ? g_Q : g_K;
    int rows = T_SEQ * nheads;
    if (warp >= rows) return;
    int t = warp / nheads;
    int h = warp - t * nheads;
    float* p = buf + (size_t)t * nheads * DH + h * DH;
    float a = p[2 * lane];
    float b = p[2 * lane + 1];
    float c = g_cos[t * 32 + lane];
    float s = g_sin[t * 32 + lane];
    __syncwarp();
    p[lane]      = a * c - b * s;
    p[lane + 32] = a * s + b * c;
    if (which == 1) {
        float ss = a * a + b * b;
        #pragma unroll
        for (int o = 16; o; o >>= 1) ss += __shfl_xor_sync(0xffffffffu, ss, o);
        if (lane == 0) g_dnm[h * T_SEQ + t] = sqrtf(fmaxf(ss, 1e-6f));
    }
}

// ---------------------------------------------------------------------------
// Core tiled fp32 GEMM-with-bias body: C[128x128 tile] = A @ B + bias.
// BK=16 slab, 8x8 per thread, 256 threads, float4 I/O, register prefetch.
// avgA != 0 : A is the 4-branch average of g_ctxh (head-major ctx layout).
// ---------------------------------------------------------------------------
__device__ __forceinline__
void gemm_tile_body(int N, int K,
                    const float* __restrict__ A,
                    const float* __restrict__ B,
                    const float* __restrict__ bias,
                    float* __restrict__ C,
                    int cRow, int cCol, int avgA) {
    const int BM = 128, BK = 16;
    __shared__ float As[BK][BM + 4];   // transposed A tile, padded
    __shared__ float Bs[BK][128];

    int tid  = threadIdx.x;
    const float* Ab = A + (avgA ? 0 : (size_t)cRow * BM * K);
    const float* Bb = B + (size_t)cCol * 128;

    int aRow = tid >> 2;                 // 0..63
    int aCol = (tid & 3) << 2;           // 0,4,8,12
    int bRow = tid >> 5;                 // 0..7
    int bCol = (tid & 31) << 2;          // 0..124
    int tr = (tid >> 4) << 3;            // 0..120
    int tc = (tid & 15) << 3;

    float acc[8][8];
    #pragma unroll
    for (int i = 0; i < 8; i++)
        #pragma unroll
        for (int j = 0; j < 8; j++) acc[i][j] = 0.f;

    // A-element loader: either plain row-major A, or branch-averaged g_ctxh.
    // For avgA: logical A[t][c], c = head*64+d ->
    //   mean_br g_ctxh[(br*16+head)*65536 + t*64 + d]
    auto loadA4 = [&](int row, int col) -> float4 {
        if (!avgA)
            return *(const float4*)(Ab + (size_t)row * K + col);
        int t = cRow * BM + row;
        int head = col >> 6;
        int d = col & 63;
        float4 s = make_float4(0.f, 0.f, 0.f, 0.f);
        #pragma unroll
        for (int br = 0; br < 4; br++) {
            const float4 v = *(const float4*)(g_ctxh +
                (size_t)(br * 16 + head) * 65536 + (size_t)t * 64 + d);
            s.x += v.x; s.y += v.y; s.z += v.z; s.w += v.w;
        }
        s.x *= 0.25f; s.y *= 0.25f; s.z *= 0.25f; s.w *= 0.25f;
        return s;
    };

    // Prologue: first slab into registers
    float4 regA[2], regB[2];
    #pragma unroll
    for (int p = 0; p < 2; p++) {
        regA[p] = loadA4(aRow + 64 * p, aCol);
        regB[p] = *(const float4*)(Bb + (size_t)(bRow + 8 * p) * N + bCol);
    }

    for (int k0 = 0; k0 < K; k0 += BK) {
        #pragma unroll
        for (int p = 0; p < 2; p++) {
            As[aCol + 0][aRow + 64 * p] = regA[p].x;
            As[aCol + 1][aRow + 64 * p] = regA[p].y;
            As[aCol + 2][aRow + 64 * p] = regA[p].z;
            As[aCol + 3][aRow + 64 * p] = regA[p].w;
            *(float4*)&Bs[bRow + 8 * p][bCol] = regB[p];
        }
        __syncthreads();

        int kn = k0 + BK;
        if (kn < K) {
            #pragma unroll
            for (int p = 0; p < 2; p++) {
                regA[p] = loadA4(aRow + 64 * p, kn + aCol);
                regB[p] = *(const float4*)(Bb + (size_t)(kn + bRow + 8 * p) * N + bCol);
            }
        }

        #pragma unroll
        for (int kk = 0; kk < BK; kk++) {
            float4 a0 = *(float4*)&As[kk][tr];
            float4 a1 = *(float4*)&As[kk][tr + 4];
            float4 b0 = *(float4*)&Bs[kk][tc];
            float4 b1 = *(float4*)&Bs[kk][tc + 4];
            float af[8] = {a0.x, a0.y, a0.z, a0.w, a1.x, a1.y, a1.z, a1.w};
            float bf[8] = {b0.x, b0.y, b0.z, b0.w, b1.x, b1.y, b1.z, b1.w};
            #pragma unroll
            for (int i = 0; i < 8; i++)
                #pragma unroll
                for (int j = 0; j < 8; j++) acc[i][j] += af[i] * bf[j];
        }
        __syncthreads();
    }

    #pragma unroll
    for (int i = 0; i < 8; i++) {
        size_t r = (size_t)cRow * BM + tr + i;
        #pragma unroll
        for (int jq = 0; jq < 2; jq++) {
            int c = cCol * 128 + tc + jq * 4;
            float4 o;
            o.x = acc[i][jq * 4 + 0] + bias[c + 0];
            o.y = acc[i][jq * 4 + 1] + bias[c + 1];
            o.z = acc[i][jq * 4 + 2] + bias[c + 2];
            o.w = acc[i][jq * 4 + 3] + bias[c + 3];
            *(float4*)(C + r * N + c) = o;
        }
    }
}

// ---------------------------------------------------------------------------
// Fused QKV projection: one launch covering
//   Q: 1024x4096 (256 CTAs), K: 1024x1024 (64 CTAs), V: 1024x4096 (256 CTAs)
// Linear block index decoded to {matrix, cRow, cCol}.
// ---------------------------------------------------------------------------
__global__ __launch_bounds__(256)
void qkv_gemm_kernel(const float* __restrict__ X,
                     const float* __restrict__ Wq, const float* __restrict__ bq,
                     const float* __restrict__ Wk, const float* __restrict__ bk,
                     const float* __restrict__ Wv, const float* __restrict__ bv) {
    int bid = blockIdx.x;
    const float* B; const float* bias; float* C; int N, cCol, cRow;
    if (bid < 256) {                       // Q
        B = Wq; bias = bq; C = g_Q; N = 4096;
        cCol = bid & 31; cRow = bid >> 5;
    } else if (bid < 320) {                // K
        int b = bid - 256;
        B = Wk; bias = bk; C = g_K; N = 1024;
        cCol = b & 7; cRow = b >> 3;
    } else {                               // V
        int b = bid - 320;
        B = Wv; bias = bv; C = g_V; N = 4096;
        cCol = b & 31; cRow = b >> 5;
    }
    gemm_tile_body(N, 1024, X, B, bias, C, cRow, cCol, 0);
}

// ---------------------------------------------------------------------------
// Output projection fused with branch average:
// out = (mean_br ctx_br) @ Wo + bo, reading g_ctxh directly.
// ---------------------------------------------------------------------------
__global__ __launch_bounds__(256)
void out_gemm_kernel(const float* __restrict__ Wo,
                     const float* __restrict__ bo,
                     float* __restrict__ out) {
    gemm_tile_body(1024, 1024, nullptr, Wo, bo, out,
                   blockIdx.y, blockIdx.x, 1);
}

// ---------------------------------------------------------------------------
// Attention. One block per (q-block of 64 rows, head). 256 threads.
// Streaming over causal K/V blocks of 64. No softmax: w >= 0, normalization
// is 1/(sum w + sink), so just accumulate sum(w*v) and sum(w).
// ---------------------------------------------------------------------------
#define SM_PITCH 65
#define SMEM_ATTN ((3 * 64 * SM_PITCH + 64) * 4)

__global__ __launch_bounds__(256)
void attn_kernel(const float* __restrict__ sink_sc,
                 const float* __restrict__ v_nulls) {
    extern __shared__ float sm[];
    float* Qs  = sm;                       // 64 x 65
    float* KVs = sm + 64 * SM_PITCH;       // 64 x 65 (K, then reused for V)
    float* Ws  = sm + 2 * 64 * SM_PITCH;   // 64 x 65
    float* dnm = sm + 3 * 64 * SM_PITCH;   // 64

    int qb = blockIdx.x;          // 0..15
    int h  = blockIdx.y;          // 0..63
    int kh = h & 15;              // K head (tiled across branches)
    int tid = threadIdx.x;
    int tr = (tid >> 4) << 2;     // row base 0..60
    int tc = (tid & 15) << 2;     // col base 0..60
    int t0 = qb * 64;

    // Load Q tile [64 x 64]
    #pragma unroll
    for (int p = 0; p < 4; p++) {
        int r = p * 16 + (tid >> 4);
        int c = (tid & 15) * 4;
        float4 v = *(const float4*)(g_Q + (size_t)(t0 + r) * 4096 + h * 64 + c);
        float* d = Qs + r * SM_PITCH + c;
        d[0] = v.x; d[1] = v.y; d[2] = v.z; d[3] = v.w;
    }

    float accO[4][4];
    #pragma unroll
    for (int i = 0; i < 4; i++)
        #pragma unroll
        for (int j = 0; j < 4; j++) accO[i][j] = 0.f;
    float Sp[4] = {0.f, 0.f, 0.f, 0.f};

    for (int kb = 0; kb <= qb; kb++) {
        __syncthreads();   // previous iteration's reads of KVs/Ws complete
        int s0 = kb * 64;
        // Load K tile
        #pragma unroll
        for (int p = 0; p < 4; p++) {
            int r = p * 16 + (tid >> 4);
            int c = (tid & 15) * 4;
            float4 v = *(const float4*)(g_K + (size_t)(s0 + r) * 1024 + kh * 64 + c);
            float* d = KVs + r * SM_PITCH + c;
            d[0] = v.x; d[1] = v.y; d[2] = v.z; d[3] = v.w;
        }
        if (tid < 64) dnm[tid] = g_dnm[kh * T_SEQ + s0 + tid];
        __syncthreads();

        // scores = Q . K^T  (4x4 per thread)
        float accS[4][4];
        #pragma unroll
        for (int i = 0; i < 4; i++)
            #pragma unroll
            for (int j = 0; j < 4; j++) accS[i][j] = 0.f;
        #pragma unroll 8
        for (int kk = 0; kk < 64; kk++) {
            float qf[4], kf[4];
            #pragma unroll
            for (int i = 0; i < 4; i++) qf[i] = Qs[(tr + i) * SM_PITCH + kk];
            #pragma unroll
            for (int j = 0; j < 4; j++) kf[j] = KVs[(tc + j) * SM_PITCH + kk];
            #pragma unroll
            for (int i = 0; i < 4; i++)
                #pragma unroll
                for (int j = 0; j < 4; j++) accS[i][j] += qf[i] * kf[j];
        }
        float rdn[4];
        #pragma unroll
        for (int j = 0; j < 4; j++) rdn[j] = ATTN_SCALE / dnm[tc + j];

        bool diag = (kb == qb);
        // elementwise: w = softplus(x) * sigmoid(SIG_SCALE * softplus(x)), mask
        #pragma unroll
        for (int i = 0; i < 4; i++) {
            #pragma unroll
            for (int j = 0; j < 4; j++) {
                float w;
                if (diag && (tc + j) > (tr + i)) {
                    w = 0.f;
                } else {
                    float x = accS[i][j] * rdn[j];
                    float e = __expf(x);
                    w = (x > 15.f) ? x : __logf(1.f + e);
                    w = w / (1.f + __expf(-SIG_SCALE * w));
                }
                Ws[(tr + i) * SM_PITCH + tc + j] = w;
                Sp[i] += w;
            }
        }
        __syncthreads();   // Ws written, K reads done -> reuse KVs for V

        // Load V tile
        #pragma unroll
        for (int p = 0; p < 4; p++) {
            int r = p * 16 + (tid >> 4);
            int c = (tid & 15) * 4;
            float4 v = *(const float4*)(g_V + (size_t)(s0 + r) * 4096 + h * 64 + c);
            float* d = KVs + r * SM_PITCH + c;
            d[0] = v.x; d[1] = v.y; d[2] = v.z; d[3] = v.w;
        }
        __syncthreads();

        // accO += W @ V
        #pragma unroll 8
        for (int kk = 0; kk < 64; kk++) {
            float wf[4], vf[4];
            #pragma unroll
            for (int i = 0; i < 4; i++) wf[i] = Ws[(tr + i) * SM_PITCH + kk];
            #pragma unroll
            for (int j = 0; j < 4; j++) vf[j] = KVs[kk * SM_PITCH + tc + j];
            #pragma unroll
            for (int i = 0; i < 4; i++)
                #pragma unroll
                for (int j = 0; j < 4; j++) accO[i][j] += wf[i] * vf[j];
        }
    }

    // Row-sum reduction across the 16 threads sharing each row group
    #pragma unroll
    for (int o = 8; o; o >>= 1) {
        #pragma unroll
        for (int i = 0; i < 4; i++)
            Sp[i] += __shfl_xor_sync(0xffffffffu, Sp[i], o, 16);
    }

    float sink = tanhf(sink_sc[h]) + 1e-6f;
    float vn[4];
    #pragma unroll
    for (int j = 0; j < 4; j++) vn[j] = v_nulls[h * 64 + tc + j];

    #pragma unroll
    for (int i = 0; i < 4; i++) {
        float alpha = 1.f / (Sp[i] + sink + 1e-6f);
        int t = t0 + tr + i;
        float4 o;
        o.x = (accO[i][0] + sink * vn[0]) * alpha;
        o.y = (accO[i][1] + sink * vn[1]) * alpha;
        o.z = (accO[i][2] + sink * vn[2]) * alpha;
        o.w = (accO[i][3] + sink * vn[3]) * alpha;
        *(float4*)(g_ctxh + (size_t)h * 65536 + (size_t)t * 64 + tc) = o;
    }
}

// ---------------------------------------------------------------------------
// Launch
// ---------------------------------------------------------------------------
extern "C" void kernel_launch(void* const* d_in, const int* in_sizes, int n_in,
                              void* d_out, int out_size) {
    const float* X     = (const float*)d_in[0];
    const float* Wq    = (const float*)d_in[1];
    const float* bq    = (const float*)d_in[2];
    const float* Wk    = (const float*)d_in[3];
    const float* bk    = (const float*)d_in[4];
    const float* Wv    = (const float*)d_in[5];
    const float* bv    = (const float*)d_in[6];
    const float* sinkp = (const float*)d_in[7];
    const float* vnull = (const float*)d_in[8];
    const float* Wo    = (const float*)d_in[9];
    const float* bo    = (const float*)d_in[10];
    float* out = (float*)d_out;

    cudaFuncSetAttribute(attn_kernel,
                         cudaFuncAttributeMaxDynamicSharedMemorySize, SMEM_ATTN);

    rope_table_kernel<<<32, 1024>>>();

    // Fused QKV projections: 256 (Q) + 64 (K) + 256 (V) CTAs in one launch
    qkv_gemm_kernel<<<576, 256>>>(X, Wq, bq, Wk, bk, Wv, bv);

    // RoPE (in place); K pass also produces per-key denominators
    rope_apply_kernel<<<(T_SEQ * HTOT) / 8, 256>>>(0);
    rope_apply_kernel<<<(T_SEQ * NHEAD) / 8, 256>>>(1);

    // Attention
    attn_kernel<<<dim3(16, 64), 256, SMEM_ATTN>>>(sinkp, vnull);

    // Output projection with fused branch average (reads g_ctxh directly)
    out_gemm_kernel<<<dim3(8, 8), 256>>>(Wo, bo, out);
}

// round 7
// speedup vs baseline: 1.3370x; 1.3370x over previous
#include <cuda_runtime.h>
#include <cuda_bf16.h>
#include <math.h>
#include <stdint.h>

#define T_SEQ 1024
#define DMODEL 1024
#define NHEAD 16
#define HTOT 64
#define DH 64
#define SIG_SCALE 1.8137993642342178f
#define ATTN_SCALE 0.125f

// ---------------------------------------------------------------------------
// Device scratch
// ---------------------------------------------------------------------------
__device__ float g_Q[T_SEQ * HTOT * DH];
__device__ float g_K[T_SEQ * NHEAD * DH];
__device__ float g_V[T_SEQ * HTOT * DH];
__device__ float g_dnm[NHEAD * T_SEQ];
__device__ float g_cos[T_SEQ * 32];
__device__ float g_sin[T_SEQ * 32];
__device__ float g_ctxh[HTOT * T_SEQ * DH];

__device__ __nv_bfloat16 g_Xh[1024 * 1024],  g_Xl[1024 * 1024];
__device__ __nv_bfloat16 g_Wqh[4096 * 1024], g_Wql[4096 * 1024];
__device__ __nv_bfloat16 g_Wkh[1024 * 1024], g_Wkl[1024 * 1024];
__device__ __nv_bfloat16 g_Wvh[4096 * 1024], g_Wvl[4096 * 1024];
__device__ __nv_bfloat16 g_Woh[1024 * 1024], g_Wol[1024 * 1024];
__device__ __nv_bfloat16 g_Ch[1024 * 1024],  g_Cl[1024 * 1024];

__device__ __forceinline__ void split2(float x, __nv_bfloat16& h, __nv_bfloat16& l) {
    h = __float2bfloat16(x);
    l = __float2bfloat16(x - __bfloat162float(h));
}

// ---------------------------------------------------------------------------
__global__ void rope_table_kernel() {
    int idx = blockIdx.x * blockDim.x + threadIdx.x;
    if (idx >= T_SEQ * 32) return;
    int t = idx >> 5;
    int i = idx & 31;
    double inv = pow(10000.0, -2.0 * (double)i / 64.0);
    double a = (double)t * inv;
    g_cos[idx] = (float)cos(a);
    g_sin[idx] = (float)sin(a);
}

__global__ void rope_apply_kernel(int which) {
    int warp = (blockIdx.x * blockDim.x + threadIdx.x) >> 5;
    int lane = threadIdx.x & 31;
    int nheads = (which == 0) ? HTOT : NHEAD;
    float* buf = (which == 0) ? g_Q : g_K;
    int rows = T_SEQ * nheads;
    if (warp >= rows) return;
    int t = warp / nheads;
    int h = warp - t * nheads;
    float* p = buf + (size_t)t * nheads * DH + h * DH;
    float a = p[2 * lane];
    float b = p[2 * lane + 1];
    float c = g_cos[t * 32 + lane];
    float s = g_sin[t * 32 + lane];
    __syncwarp();
    p[lane]      = a * c - b * s;
    p[lane + 32] = a * s + b * c;
    if (which == 1) {
        float ss = a * a + b * b;
        #pragma unroll
        for (int o = 16; o; o >>= 1) ss += __shfl_xor_sync(0xffffffffu, ss, o);
        if (lane == 0) g_dnm[h * T_SEQ + t] = sqrtf(fmaxf(ss, 1e-6f));
    }
}

// ---------------------------------------------------------------------------
// Operand conversion kernels
// ---------------------------------------------------------------------------
__global__ void convert_x_kernel(const float* __restrict__ X) {
    int i = blockIdx.x * blockDim.x + threadIdx.x;
    split2(X[i], g_Xh[i], g_Xl[i]);
}

__global__ void tconv_kernel(const float* __restrict__ src, int K, int N, int which) {
    __shared__ float s[32][33];
    int n = blockIdx.x * 32 + threadIdx.x;
    int k = blockIdx.y * 32 + threadIdx.y;
    s[threadIdx.y][threadIdx.x] = src[(size_t)k * N + n];
    __syncthreads();
    int nn = blockIdx.x * 32 + threadIdx.y;
    int kk = blockIdx.y * 32 + threadIdx.x;
    float v = s[threadIdx.x][threadIdx.y];
    __nv_bfloat16 h, l;
    split2(v, h, l);
    size_t o = (size_t)nn * K + kk;
    if (which == 0)      { g_Wqh[o] = h; g_Wql[o] = l; }
    else if (which == 1) { g_Wkh[o] = h; g_Wkl[o] = l; }
    else if (which == 2) { g_Wvh[o] = h; g_Wvl[o] = l; }
    else                 { g_Woh[o] = h; g_Wol[o] = l; }
}

__global__ void avg_convert_kernel() {
    int idx = blockIdx.x * blockDim.x + threadIdx.x;
    int t = idx >> 10;
    int c = idx & 1023;
    int head = c >> 6;
    int d = c & 63;
    float s = 0.f;
    #pragma unroll
    for (int br = 0; br < 4; br++)
        s += g_ctxh[(size_t)(br * 16 + head) * 65536 + (size_t)t * 64 + d];
    split2(0.25f * s, g_Ch[idx], g_Cl[idx]);
}

// ---------------------------------------------------------------------------
// bf16 mma.sync m16n8k16, fp32 accumulate
// ---------------------------------------------------------------------------
__device__ __forceinline__ void mma_bf16(float c[4],
                                         uint32_t a0, uint32_t a1, uint32_t a2, uint32_t a3,
                                         uint32_t b0, uint32_t b1) {
    asm volatile(
        "mma.sync.aligned.m16n8k16.row.col.f32.bf16.bf16.f32 "
        "{%0,%1,%2,%3}, {%4,%5,%6,%7}, {%8,%9}, {%0,%1,%2,%3};\n"
        : "+f"(c[0]), "+f"(c[1]), "+f"(c[2]), "+f"(c[3])
        : "r"(a0), "r"(a1), "r"(a2), "r"(a3), "r"(b0), "r"(b1));
}

// ---------------------------------------------------------------------------
// Split-bf16 tensor-core GEMM tile body.
// C[128x128 tile] = (Ah+Al)(Bh+Bl)^T + bias    (Al*Bl dropped, ~2^-16 rel)
// A: [M][K] row-major hi/lo. B: [N][K] row-major (pre-transposed weights).
// 256 threads = 8 warps (2x4), warp tile 64x32, fp32 accum.
// ---------------------------------------------------------------------------
#define GP 40

__device__ void mma_gemm_body(const __nv_bfloat16* __restrict__ Ah,
                              const __nv_bfloat16* __restrict__ Al,
                              const __nv_bfloat16* __restrict__ Bh,
                              const __nv_bfloat16* __restrict__ Bl,
                              const float* __restrict__ bias,
                              float* __restrict__ C,
                              int N, int K, int cRow, int cCol) {
    __shared__ __nv_bfloat16 sAh[128][GP], sAl[128][GP];
    __shared__ __nv_bfloat16 sBh[128][GP], sBl[128][GP];

    int tid  = threadIdx.x;
    int lane = tid & 31;
    int w    = tid >> 5;
    int wr   = w >> 2;
    int wc   = w & 3;
    int rowBase = cRow * 128;
    int colBase = cCol * 128;

    float acc[4][4][4];
    #pragma unroll
    for (int i = 0; i < 4; i++)
        #pragma unroll
        for (int j = 0; j < 4; j++)
            #pragma unroll
            for (int q = 0; q < 4; q++) acc[i][j][q] = 0.f;

    for (int k0 = 0; k0 < K; k0 += 32) {
        __syncthreads();
        #pragma unroll
        for (int i = 0; i < 4; i++) {
            int idx = i * 256 + tid;
            int r = idx >> 3;
            int kq = (idx & 7) << 2;
            *(uint2*)&sAh[r][kq] = *(const uint2*)(Ah + (size_t)(rowBase + r) * K + k0 + kq);
            *(uint2*)&sAl[r][kq] = *(const uint2*)(Al + (size_t)(rowBase + r) * K + k0 + kq);
            *(uint2*)&sBh[r][kq] = *(const uint2*)(Bh + (size_t)(colBase + r) * K + k0 + kq);
            *(uint2*)&sBl[r][kq] = *(const uint2*)(Bl + (size_t)(colBase + r) * K + k0 + kq);
        }
        __syncthreads();

        #pragma unroll
        for (int ks = 0; ks < 2; ks++) {
            int kk = ks * 16 + (lane & 3) * 2;
            uint32_t bh[4][2], bl[4][2];
            #pragma unroll
            for (int nb = 0; nb < 4; nb++) {
                int n = wc * 32 + nb * 8 + (lane >> 2);
                bh[nb][0] = *(const uint32_t*)&sBh[n][kk];
                bh[nb][1] = *(const uint32_t*)&sBh[n][kk + 8];
                bl[nb][0] = *(const uint32_t*)&sBl[n][kk];
                bl[nb][1] = *(const uint32_t*)&sBl[n][kk + 8];
            }
            #pragma unroll
            for (int ma = 0; ma < 4; ma++) {
                int r0 = wr * 64 + ma * 16 + (lane >> 2);
                uint32_t ah0 = *(const uint32_t*)&sAh[r0][kk];
                uint32_t ah1 = *(const uint32_t*)&sAh[r0 + 8][kk];
                uint32_t ah2 = *(const uint32_t*)&sAh[r0][kk + 8];
                uint32_t ah3 = *(const uint32_t*)&sAh[r0 + 8][kk + 8];
                uint32_t al0 = *(const uint32_t*)&sAl[r0][kk];
                uint32_t al1 = *(const uint32_t*)&sAl[r0 + 8][kk];
                uint32_t al2 = *(const uint32_t*)&sAl[r0][kk + 8];
                uint32_t al3 = *(const uint32_t*)&sAl[r0 + 8][kk + 8];
                #pragma unroll
                for (int nb = 0; nb < 4; nb++) {
                    mma_bf16(acc[ma][nb], ah0, ah1, ah2, ah3, bh[nb][0], bh[nb][1]);
                    mma_bf16(acc[ma][nb], ah0, ah1, ah2, ah3, bl[nb][0], bl[nb][1]);
                    mma_bf16(acc[ma][nb], al0, al1, al2, al3, bh[nb][0], bh[nb][1]);
                }
            }
        }
    }

    #pragma unroll
    for (int ma = 0; ma < 4; ma++) {
        int row = rowBase + wr * 64 + ma * 16 + (lane >> 2);
        #pragma unroll
        for (int nb = 0; nb < 4; nb++) {
            int col = colBase + wc * 32 + nb * 8 + (lane & 3) * 2;
            float b0 = bias[col], b1 = bias[col + 1];
            *(float2*)(C + (size_t)row * N + col) =
                make_float2(acc[ma][nb][0] + b0, acc[ma][nb][1] + b1);
            *(float2*)(C + (size_t)(row + 8) * N + col) =
                make_float2(acc[ma][nb][2] + b0, acc[ma][nb][3] + b1);
        }
    }
}

__global__ __launch_bounds__(256)
void qkv_mma_kernel(const float* __restrict__ bq,
                    const float* __restrict__ bk,
                    const float* __restrict__ bv) {
    int bid = blockIdx.x;
    if (bid < 256) {
        mma_gemm_body(g_Xh, g_Xl, g_Wqh, g_Wql, bq, g_Q, 4096, 1024, bid >> 5, bid & 31);
    } else if (bid < 320) {
        int b = bid - 256;
        mma_gemm_body(g_Xh, g_Xl, g_Wkh, g_Wkl, bk, g_K, 1024, 1024, b >> 3, b & 7);
    } else {
        int b = bid - 320;
        mma_gemm_body(g_Xh, g_Xl, g_Wvh, g_Wvl, bv, g_V, 4096, 1024, b >> 5, b & 31);
    }
}

__global__ __launch_bounds__(256)
void out_mma_kernel(const float* __restrict__ bo, float* __restrict__ out) {
    mma_gemm_body(g_Ch, g_Cl, g_Woh, g_Wol, bo, out, 1024, 1024, blockIdx.y, blockIdx.x);
}

// ---------------------------------------------------------------------------
// Attention (unchanged from R4 measured-correct version)
// ---------------------------------------------------------------------------
#define SM_PITCH 65
#define SMEM_ATTN ((3 * 64 * SM_PITCH + 64) * 4)

__global__ __launch_bounds__(256)
void attn_kernel(const float* __restrict__ sink_sc,
                 const float* __restrict__ v_nulls) {
    extern __shared__ float sm[];
    float* Qs  = sm;
    float* KVs = sm + 64 * SM_PITCH;
    float* Ws  = sm + 2 * 64 * SM_PITCH;
    float* dnm = sm + 3 * 64 * SM_PITCH;

    int qb = blockIdx.x;
    int h  = blockIdx.y;
    int kh = h & 15;
    int tid = threadIdx.x;
    int tr = (tid >> 4) << 2;
    int tc = (tid & 15) << 2;
    int t0 = qb * 64;

    #pragma unroll
    for (int p = 0; p < 4; p++) {
        int r = p * 16 + (tid >> 4);
        int c = (tid & 15) * 4;
        float4 v = *(const float4*)(g_Q + (size_t)(t0 + r) * 4096 + h * 64 + c);
        float* d = Qs + r * SM_PITCH + c;
        d[0] = v.x; d[1] = v.y; d[2] = v.z; d[3] = v.w;
    }

    float accO[4][4];
    #pragma unroll
    for (int i = 0; i < 4; i++)
        #pragma unroll
        for (int j = 0; j < 4; j++) accO[i][j] = 0.f;
    float Sp[4] = {0.f, 0.f, 0.f, 0.f};

    for (int kb = 0; kb <= qb; kb++) {
        __syncthreads();
        int s0 = kb * 64;
        #pragma unroll
        for (int p = 0; p < 4; p++) {
            int r = p * 16 + (tid >> 4);
            int c = (tid & 15) * 4;
            float4 v = *(const float4*)(g_K + (size_t)(s0 + r) * 1024 + kh * 64 + c);
            float* d = KVs + r * SM_PITCH + c;
            d[0] = v.x; d[1] = v.y; d[2] = v.z; d[3] = v.w;
        }
        if (tid < 64) dnm[tid] = g_dnm[kh * T_SEQ + s0 + tid];
        __syncthreads();

        float accS[4][4];
        #pragma unroll
        for (int i = 0; i < 4; i++)
            #pragma unroll
            for (int j = 0; j < 4; j++) accS[i][j] = 0.f;
        #pragma unroll 8
        for (int kk = 0; kk < 64; kk++) {
            float qf[4], kf[4];
            #pragma unroll
            for (int i = 0; i < 4; i++) qf[i] = Qs[(tr + i) * SM_PITCH + kk];
            #pragma unroll
            for (int j = 0; j < 4; j++) kf[j] = KVs[(tc + j) * SM_PITCH + kk];
            #pragma unroll
            for (int i = 0; i < 4; i++)
                #pragma unroll
                for (int j = 0; j < 4; j++) accS[i][j] += qf[i] * kf[j];
        }
        float rdn[4];
        #pragma unroll
        for (int j = 0; j < 4; j++) rdn[j] = ATTN_SCALE / dnm[tc + j];

        bool diag = (kb == qb);
        #pragma unroll
        for (int i = 0; i < 4; i++) {
            #pragma unroll
            for (int j = 0; j < 4; j++) {
                float w;
                if (diag && (tc + j) > (tr + i)) {
                    w = 0.f;
                } else {
                    float x = accS[i][j] * rdn[j];
                    float e = __expf(x);
                    w = (x > 15.f) ? x : __logf(1.f + e);
                    w = w / (1.f + __expf(-SIG_SCALE * w));
                }
                Ws[(tr + i) * SM_PITCH + tc + j] = w;
                Sp[i] += w;
            }
        }
        __syncthreads();

        #pragma unroll
        for (int p = 0; p < 4; p++) {
            int r = p * 16 + (tid >> 4);
            int c = (tid & 15) * 4;
            float4 v = *(const float4*)(g_V + (size_t)(s0 + r) * 4096 + h * 64 + c);
            float* d = KVs + r * SM_PITCH + c;
            d[0] = v.x; d[1] = v.y; d[2] = v.z; d[3] = v.w;
        }
        __syncthreads();

        #pragma unroll 8
        for (int kk = 0; kk < 64; kk++) {
            float wf[4], vf[4];
            #pragma unroll
            for (int i = 0; i < 4; i++) wf[i] = Ws[(tr + i) * SM_PITCH + kk];
            #pragma unroll
            for (int j = 0; j < 4; j++) vf[j] = KVs[kk * SM_PITCH + tc + j];
            #pragma unroll
            for (int i = 0; i < 4; i++)
                #pragma unroll
                for (int j = 0; j < 4; j++) accO[i][j] += wf[i] * vf[j];
        }
    }

    #pragma unroll
    for (int o = 8; o; o >>= 1) {
        #pragma unroll
        for (int i = 0; i < 4; i++)
            Sp[i] += __shfl_xor_sync(0xffffffffu, Sp[i], o, 16);
    }

    float sink = tanhf(sink_sc[h]) + 1e-6f;
    float vn[4];
    #pragma unroll
    for (int j = 0; j < 4; j++) vn[j] = v_nulls[h * 64 + tc + j];

    #pragma unroll
    for (int i = 0; i < 4; i++) {
        float alpha = 1.f / (Sp[i] + sink + 1e-6f);
        int t = t0 + tr + i;
        float4 o;
        o.x = (accO[i][0] + sink * vn[0]) * alpha;
        o.y = (accO[i][1] + sink * vn[1]) * alpha;
        o.z = (accO[i][2] + sink * vn[2]) * alpha;
        o.w = (accO[i][3] + sink * vn[3]) * alpha;
        *(float4*)(g_ctxh + (size_t)h * 65536 + (size_t)t * 64 + tc) = o;
    }
}

// ---------------------------------------------------------------------------
// Launch
// ---------------------------------------------------------------------------
extern "C" void kernel_launch(void* const* d_in, const int* in_sizes, int n_in,
                              void* d_out, int out_size) {
    const float* X     = (const float*)d_in[0];
    const float* Wq    = (const float*)d_in[1];
    const float* bq    = (const float*)d_in[2];
    const float* Wk    = (const float*)d_in[3];
    const float* bk    = (const float*)d_in[4];
    const float* Wv    = (const float*)d_in[5];
    const float* bv    = (const float*)d_in[6];
    const float* sinkp = (const float*)d_in[7];
    const float* vnull = (const float*)d_in[8];
    const float* Wo    = (const float*)d_in[9];
    const float* bo    = (const float*)d_in[10];
    float* out = (float*)d_out;

    cudaFuncSetAttribute(attn_kernel,
                         cudaFuncAttributeMaxDynamicSharedMemorySize, SMEM_ATTN);

    rope_table_kernel<<<32, 1024>>>();

    // Operand split/convert for tensor-core GEMMs
    convert_x_kernel<<<(1024 * 1024) / 256, 256>>>(X);
    tconv_kernel<<<dim3(128, 32), dim3(32, 32)>>>(Wq, 1024, 4096, 0);
    tconv_kernel<<<dim3(32, 32),  dim3(32, 32)>>>(Wk, 1024, 1024, 1);
    tconv_kernel<<<dim3(128, 32), dim3(32, 32)>>>(Wv, 1024, 4096, 2);
    tconv_kernel<<<dim3(32, 32),  dim3(32, 32)>>>(Wo, 1024, 1024, 3);

    // Fused QKV projections on tensor cores
    qkv_mma_kernel<<<576, 256>>>(bq, bk, bv);

    // RoPE (in place); K pass also produces per-key denominators
    rope_apply_kernel<<<(T_SEQ * HTOT) / 8, 256>>>(0);
    rope_apply_kernel<<<(T_SEQ * NHEAD) / 8, 256>>>(1);

    // Attention
    attn_kernel<<<dim3(16, 64), 256, SMEM_ATTN>>>(sinkp, vnull);

    // Branch-average + split, then output projection on tensor cores
    avg_convert_kernel<<<(T_SEQ * DMODEL) / 256, 256>>>();
    out_mma_kernel<<<dim3(8, 8), 256>>>(bo, out);
}

// round 13
// speedup vs baseline: 1.6520x; 1.2357x over previous
#include <cuda_runtime.h>
#include <cuda_bf16.h>
#include <math.h>
#include <stdint.h>

#define T_SEQ 1024
#define DMODEL 1024
#define NHEAD 16
#define HTOT 64
#define DH 64
#define SIG_SCALE 1.8137993642342178f
#define ATTN_SCALE 0.125f

// ---------------------------------------------------------------------------
// Device scratch
// ---------------------------------------------------------------------------
__device__ float g_Q[T_SEQ * HTOT * DH];
__device__ float g_K[T_SEQ * NHEAD * DH];
__device__ float g_V[T_SEQ * HTOT * DH];
__device__ float g_dnm[NHEAD * T_SEQ];
__device__ float g_cos[T_SEQ * 32];
__device__ float g_sin[T_SEQ * 32];
__device__ float g_ctxh[HTOT * T_SEQ * DH];

__device__ __nv_bfloat16 g_Xh[1024 * 1024],  g_Xl[1024 * 1024];
__device__ __nv_bfloat16 g_Wqh[4096 * 1024], g_Wql[4096 * 1024];
__device__ __nv_bfloat16 g_Wkh[1024 * 1024], g_Wkl[1024 * 1024];
__device__ __nv_bfloat16 g_Wvh[4096 * 1024], g_Wvl[4096 * 1024];
__device__ __nv_bfloat16 g_Woh[1024 * 1024], g_Wol[1024 * 1024];
__device__ __nv_bfloat16 g_Ch[1024 * 1024],  g_Cl[1024 * 1024];

__device__ __forceinline__ void split2(float x, __nv_bfloat16& h, __nv_bfloat16& l) {
    h = __float2bfloat16(x);
    l = __float2bfloat16(x - __bfloat162float(h));
}

// ---------------------------------------------------------------------------
__global__ void rope_table_kernel() {
    int idx = blockIdx.x * blockDim.x + threadIdx.x;
    if (idx >= T_SEQ * 32) return;
    int t = idx >> 5;
    int i = idx & 31;
    double inv = pow(10000.0, -2.0 * (double)i / 64.0);
    double a = (double)t * inv;
    g_cos[idx] = (float)cos(a);
    g_sin[idx] = (float)sin(a);
}

__global__ void rope_apply_kernel(int which) {
    int warp = (blockIdx.x * blockDim.x + threadIdx.x) >> 5;
    int lane = threadIdx.x & 31;
    int nheads = (which == 0) ? HTOT : NHEAD;
    float* buf = (which == 0) ? g_Q : g_K;
    int rows = T_SEQ * nheads;
    if (warp >= rows) return;
    int t = warp / nheads;
    int h = warp - t * nheads;
    float* p = buf + (size_t)t * nheads * DH + h * DH;
    float a = p[2 * lane];
    float b = p[2 * lane + 1];
    float c = g_cos[t * 32 + lane];
    float s = g_sin[t * 32 + lane];
    __syncwarp();
    p[lane]      = a * c - b * s;
    p[lane + 32] = a * s + b * c;
    if (which == 1) {
        float ss = a * a + b * b;
        #pragma unroll
        for (int o = 16; o; o >>= 1) ss += __shfl_xor_sync(0xffffffffu, ss, o);
        if (lane == 0) g_dnm[h * T_SEQ + t] = sqrtf(fmaxf(ss, 1e-6f));
    }
}

// ---------------------------------------------------------------------------
// Operand conversion kernels
// ---------------------------------------------------------------------------
__global__ void convert_x_kernel(const float* __restrict__ X) {
    int i = blockIdx.x * blockDim.x + threadIdx.x;
    split2(X[i], g_Xh[i], g_Xl[i]);
}

__global__ void tconv_kernel(const float* __restrict__ src, int K, int N, int which) {
    __shared__ float s[32][33];
    int n = blockIdx.x * 32 + threadIdx.x;
    int k = blockIdx.y * 32 + threadIdx.y;
    s[threadIdx.y][threadIdx.x] = src[(size_t)k * N + n];
    __syncthreads();
    int nn = blockIdx.x * 32 + threadIdx.y;
    int kk = blockIdx.y * 32 + threadIdx.x;
    float v = s[threadIdx.x][threadIdx.y];
    __nv_bfloat16 h, l;
    split2(v, h, l);
    size_t o = (size_t)nn * K + kk;
    if (which == 0)      { g_Wqh[o] = h; g_Wql[o] = l; }
    else if (which == 1) { g_Wkh[o] = h; g_Wkl[o] = l; }
    else if (which == 2) { g_Wvh[o] = h; g_Wvl[o] = l; }
    else                 { g_Woh[o] = h; g_Wol[o] = l; }
}

__global__ void avg_convert_kernel() {
    int idx = blockIdx.x * blockDim.x + threadIdx.x;
    int t = idx >> 10;
    int c = idx & 1023;
    int head = c >> 6;
    int d = c & 63;
    float s = 0.f;
    #pragma unroll
    for (int br = 0; br < 4; br++)
        s += g_ctxh[(size_t)(br * 16 + head) * 65536 + (size_t)t * 64 + d];
    split2(0.25f * s, g_Ch[idx], g_Cl[idx]);
}

// ---------------------------------------------------------------------------
// bf16 mma.sync m16n8k16, fp32 accumulate
// ---------------------------------------------------------------------------
__device__ __forceinline__ void mma_bf16(float c[4],
                                         uint32_t a0, uint32_t a1, uint32_t a2, uint32_t a3,
                                         uint32_t b0, uint32_t b1) {
    asm volatile(
        "mma.sync.aligned.m16n8k16.row.col.f32.bf16.bf16.f32 "
        "{%0,%1,%2,%3}, {%4,%5,%6,%7}, {%8,%9}, {%0,%1,%2,%3};\n"
        : "+f"(c[0]), "+f"(c[1]), "+f"(c[2]), "+f"(c[3])
        : "r"(a0), "r"(a1), "r"(a2), "r"(a3), "r"(b0), "r"(b1));
}

// ---------------------------------------------------------------------------
// Split-bf16 tensor-core GEMM tile body (validated in R7).
// ---------------------------------------------------------------------------
#define GP 40

__device__ void mma_gemm_body(const __nv_bfloat16* __restrict__ Ah,
                              const __nv_bfloat16* __restrict__ Al,
                              const __nv_bfloat16* __restrict__ Bh,
                              const __nv_bfloat16* __restrict__ Bl,
                              const float* __restrict__ bias,
                              float* __restrict__ C,
                              int N, int K, int cRow, int cCol) {
    __shared__ __nv_bfloat16 sAh[128][GP], sAl[128][GP];
    __shared__ __nv_bfloat16 sBh[128][GP], sBl[128][GP];

    int tid  = threadIdx.x;
    int lane = tid & 31;
    int w    = tid >> 5;
    int wr   = w >> 2;
    int wc   = w & 3;
    int rowBase = cRow * 128;
    int colBase = cCol * 128;

    float acc[4][4][4];
    #pragma unroll
    for (int i = 0; i < 4; i++)
        #pragma unroll
        for (int j = 0; j < 4; j++)
            #pragma unroll
            for (int q = 0; q < 4; q++) acc[i][j][q] = 0.f;

    for (int k0 = 0; k0 < K; k0 += 32) {
        __syncthreads();
        #pragma unroll
        for (int i = 0; i < 4; i++) {
            int idx = i * 256 + tid;
            int r = idx >> 3;
            int kq = (idx & 7) << 2;
            *(uint2*)&sAh[r][kq] = *(const uint2*)(Ah + (size_t)(rowBase + r) * K + k0 + kq);
            *(uint2*)&sAl[r][kq] = *(const uint2*)(Al + (size_t)(rowBase + r) * K + k0 + kq);
            *(uint2*)&sBh[r][kq] = *(const uint2*)(Bh + (size_t)(colBase + r) * K + k0 + kq);
            *(uint2*)&sBl[r][kq] = *(const uint2*)(Bl + (size_t)(colBase + r) * K + k0 + kq);
        }
        __syncthreads();

        #pragma unroll
        for (int ks = 0; ks < 2; ks++) {
            int kk = ks * 16 + (lane & 3) * 2;
            uint32_t bh[4][2], bl[4][2];
            #pragma unroll
            for (int nb = 0; nb < 4; nb++) {
                int n = wc * 32 + nb * 8 + (lane >> 2);
                bh[nb][0] = *(const uint32_t*)&sBh[n][kk];
                bh[nb][1] = *(const uint32_t*)&sBh[n][kk + 8];
                bl[nb][0] = *(const uint32_t*)&sBl[n][kk];
                bl[nb][1] = *(const uint32_t*)&sBl[n][kk + 8];
            }
            #pragma unroll
            for (int ma = 0; ma < 4; ma++) {
                int r0 = wr * 64 + ma * 16 + (lane >> 2);
                uint32_t ah0 = *(const uint32_t*)&sAh[r0][kk];
                uint32_t ah1 = *(const uint32_t*)&sAh[r0 + 8][kk];
                uint32_t ah2 = *(const uint32_t*)&sAh[r0][kk + 8];
                uint32_t ah3 = *(const uint32_t*)&sAh[r0 + 8][kk + 8];
                uint32_t al0 = *(const uint32_t*)&sAl[r0][kk];
                uint32_t al1 = *(const uint32_t*)&sAl[r0 + 8][kk];
                uint32_t al2 = *(const uint32_t*)&sAl[r0][kk + 8];
                uint32_t al3 = *(const uint32_t*)&sAl[r0 + 8][kk + 8];
                #pragma unroll
                for (int nb = 0; nb < 4; nb++) {
                    mma_bf16(acc[ma][nb], ah0, ah1, ah2, ah3, bh[nb][0], bh[nb][1]);
                    mma_bf16(acc[ma][nb], ah0, ah1, ah2, ah3, bl[nb][0], bl[nb][1]);
                    mma_bf16(acc[ma][nb], al0, al1, al2, al3, bh[nb][0], bh[nb][1]);
                }
            }
        }
    }

    #pragma unroll
    for (int ma = 0; ma < 4; ma++) {
        int row = rowBase + wr * 64 + ma * 16 + (lane >> 2);
        #pragma unroll
        for (int nb = 0; nb < 4; nb++) {
            int col = colBase + wc * 32 + nb * 8 + (lane & 3) * 2;
            float b0 = bias[col], b1 = bias[col + 1];
            *(float2*)(C + (size_t)row * N + col) =
                make_float2(acc[ma][nb][0] + b0, acc[ma][nb][1] + b1);
            *(float2*)(C + (size_t)(row + 8) * N + col) =
                make_float2(acc[ma][nb][2] + b0, acc[ma][nb][3] + b1);
        }
    }
}

__global__ __launch_bounds__(256)
void qkv_mma_kernel(const float* __restrict__ bq,
                    const float* __restrict__ bk,
                    const float* __restrict__ bv) {
    int bid = blockIdx.x;
    if (bid < 256) {
        mma_gemm_body(g_Xh, g_Xl, g_Wqh, g_Wql, bq, g_Q, 4096, 1024, bid >> 5, bid & 31);
    } else if (bid < 320) {
        int b = bid - 256;
        mma_gemm_body(g_Xh, g_Xl, g_Wkh, g_Wkl, bk, g_K, 1024, 1024, b >> 3, b & 7);
    } else {
        int b = bid - 320;
        mma_gemm_body(g_Xh, g_Xl, g_Wvh, g_Wvl, bv, g_V, 4096, 1024, b >> 5, b & 31);
    }
}

__global__ __launch_bounds__(256)
void out_mma_kernel(const float* __restrict__ bo, float* __restrict__ out) {
    mma_gemm_body(g_Ch, g_Cl, g_Woh, g_Wol, bo, out, 1024, 1024, blockIdx.y, blockIdx.x);
}

// ---------------------------------------------------------------------------
// Attention on tensor cores (bf16-split mma). Block = (qb 64 rows, head h).
// 256 threads = 8 warps in 4(m) x 2(n); warp tile 16x32 (1 m-atom, 4 n-atoms).
// Streaming over causal K/V blocks of 64; no softmax (w>=0, alpha=1/(sum+sink)).
// ---------------------------------------------------------------------------
#define AP 72   // bf16 smem pitch (conflict-free for 32-bit fragment I/O)
#define SMEM_ATTN2 (6 * 64 * AP * 2 + 64 * 4 + 128 * 4)

__device__ __forceinline__ float act_mask(float x, int r, int c, bool diagb) {
    if (diagb && c > r) return 0.f;
    float e = __expf(x);
    float wv = (x > 15.f) ? x : __logf(1.f + e);
    return wv / (1.f + __expf(-SIG_SCALE * wv));
}

__global__ __launch_bounds__(256)
void attn_mma_kernel(const float* __restrict__ sink_sc,
                     const float* __restrict__ v_nulls) {
    extern __shared__ char smraw[];
    __nv_bfloat16* sQh = (__nv_bfloat16*)smraw;
    __nv_bfloat16* sQl = sQh + 64 * AP;
    __nv_bfloat16* sKh = sQl + 64 * AP;   // K tile, later V^T tile
    __nv_bfloat16* sKl = sKh + 64 * AP;
    __nv_bfloat16* sWh = sKl + 64 * AP;
    __nv_bfloat16* sWl = sWh + 64 * AP;
    float* dnm  = (float*)(sWl + 64 * AP);   // 64
    float* rsum = dnm + 64;                  // [2][64]

    int qb = blockIdx.x, h = blockIdx.y, kh = h & 15;
    int tid = threadIdx.x, lane = tid & 31, w = tid >> 5;
    int wm = w >> 1, wn = w & 1;
    int g = lane >> 2, tq = lane & 3;
    int t0 = qb * 64;
    int r0 = wm * 16 + g;                    // fragment rows r0, r0+8

    // Load + split Q tile [64 x 64]
    #pragma unroll
    for (int i = 0; i < 4; i++) {
        int idx = i * 256 + tid;
        int r = idx >> 4, c = (idx & 15) * 4;
        float4 v = *(const float4*)(g_Q + (size_t)(t0 + r) * 4096 + h * 64 + c);
        __nv_bfloat16 h0, l0, h1, l1, h2, l2, h3, l3;
        split2(v.x, h0, l0); split2(v.y, h1, l1);
        split2(v.z, h2, l2); split2(v.w, h3, l3);
        __nv_bfloat162 p;
        p.x = h0; p.y = h1; *(__nv_bfloat162*)&sQh[r * AP + c]     = p;
        p.x = h2; p.y = h3; *(__nv_bfloat162*)&sQh[r * AP + c + 2] = p;
        p.x = l0; p.y = l1; *(__nv_bfloat162*)&sQl[r * AP + c]     = p;
        p.x = l2; p.y = l3; *(__nv_bfloat162*)&sQl[r * AP + c + 2] = p;
    }

    float accO[4][4];
    #pragma unroll
    for (int i = 0; i < 4; i++)
        #pragma unroll
        for (int j = 0; j < 4; j++) accO[i][j] = 0.f;
    float sp0 = 0.f, sp1 = 0.f;

    for (int kb = 0; kb <= qb; kb++) {
        __syncthreads();   // prior PV mma reads of sK/sW complete; Q store covered
        int s0 = kb * 64;

        // Load + split K tile ([s][d] == B-operand [n][k] layout)
        #pragma unroll
        for (int i = 0; i < 4; i++) {
            int idx = i * 256 + tid;
            int r = idx >> 4, c = (idx & 15) * 4;
            float4 v = *(const float4*)(g_K + (size_t)(s0 + r) * 1024 + kh * 64 + c);
            __nv_bfloat16 h0, l0, h1, l1, h2, l2, h3, l3;
            split2(v.x, h0, l0); split2(v.y, h1, l1);
            split2(v.z, h2, l2); split2(v.w, h3, l3);
            __nv_bfloat162 p;
            p.x = h0; p.y = h1; *(__nv_bfloat162*)&sKh[r * AP + c]     = p;
            p.x = h2; p.y = h3; *(__nv_bfloat162*)&sKh[r * AP + c + 2] = p;
            p.x = l0; p.y = l1; *(__nv_bfloat162*)&sKl[r * AP + c]     = p;
            p.x = l2; p.y = l3; *(__nv_bfloat162*)&sKl[r * AP + c + 2] = p;
        }
        if (tid < 64) dnm[tid] = g_dnm[kh * T_SEQ + s0 + tid];
        __syncthreads();

        // S = Q K^T  (3-term split)
        float accS[4][4];
        #pragma unroll
        for (int i = 0; i < 4; i++)
            #pragma unroll
            for (int j = 0; j < 4; j++) accS[i][j] = 0.f;
        #pragma unroll
        for (int ks = 0; ks < 4; ks++) {
            int kk = ks * 16 + tq * 2;
            uint32_t ah0 = *(const uint32_t*)&sQh[r0 * AP + kk];
            uint32_t ah1 = *(const uint32_t*)&sQh[(r0 + 8) * AP + kk];
            uint32_t ah2 = *(const uint32_t*)&sQh[r0 * AP + kk + 8];
            uint32_t ah3 = *(const uint32_t*)&sQh[(r0 + 8) * AP + kk + 8];
            uint32_t al0 = *(const uint32_t*)&sQl[r0 * AP + kk];
            uint32_t al1 = *(const uint32_t*)&sQl[(r0 + 8) * AP + kk];
            uint32_t al2 = *(const uint32_t*)&sQl[r0 * AP + kk + 8];
            uint32_t al3 = *(const uint32_t*)&sQl[(r0 + 8) * AP + kk + 8];
            #pragma unroll
            for (int nb = 0; nb < 4; nb++) {
                int n = wn * 32 + nb * 8 + g;
                uint32_t bh0 = *(const uint32_t*)&sKh[n * AP + kk];
                uint32_t bh1 = *(const uint32_t*)&sKh[n * AP + kk + 8];
                uint32_t bl0 = *(const uint32_t*)&sKl[n * AP + kk];
                uint32_t bl1 = *(const uint32_t*)&sKl[n * AP + kk + 8];
                mma_bf16(accS[nb], ah0, ah1, ah2, ah3, bh0, bh1);
                mma_bf16(accS[nb], ah0, ah1, ah2, ah3, bl0, bl1);
                mma_bf16(accS[nb], al0, al1, al2, al3, bh0, bh1);
            }
        }
        __syncthreads();   // K reads done -> reuse buffer for V^T

        // Load V, store transposed + split: sK* <- V^T [d][s]
        #pragma unroll
        for (int i = 0; i < 4; i++) {
            int idx = i * 256 + tid;
            int s = idx >> 4, c = (idx & 15) * 4;
            float4 v = *(const float4*)(g_V + (size_t)(s0 + s) * 4096 + h * 64 + c);
            __nv_bfloat16 hh, ll;
            split2(v.x, hh, ll); sKh[(c + 0) * AP + s] = hh; sKl[(c + 0) * AP + s] = ll;
            split2(v.y, hh, ll); sKh[(c + 1) * AP + s] = hh; sKl[(c + 1) * AP + s] = ll;
            split2(v.z, hh, ll); sKh[(c + 2) * AP + s] = hh; sKl[(c + 2) * AP + s] = ll;
            split2(v.w, hh, ll); sKh[(c + 3) * AP + s] = hh; sKl[(c + 3) * AP + s] = ll;
        }

        // Activation + row sums + split-store W
        bool diagb = (kb == qb);
        #pragma unroll
        for (int nb = 0; nb < 4; nb++) {
            int cb = wn * 32 + nb * 8 + tq * 2;
            float rdn0 = ATTN_SCALE / dnm[cb];
            float rdn1 = ATTN_SCALE / dnm[cb + 1];
            float w00 = act_mask(accS[nb][0] * rdn0, r0,     cb,     diagb);
            float w01 = act_mask(accS[nb][1] * rdn1, r0,     cb + 1, diagb);
            float w10 = act_mask(accS[nb][2] * rdn0, r0 + 8, cb,     diagb);
            float w11 = act_mask(accS[nb][3] * rdn1, r0 + 8, cb + 1, diagb);
            sp0 += w00 + w01;
            sp1 += w10 + w11;
            __nv_bfloat16 h0, l0, h1, l1;
            __nv_bfloat162 p;
            split2(w00, h0, l0); split2(w01, h1, l1);
            p.x = h0; p.y = h1; *(__nv_bfloat162*)&sWh[r0 * AP + cb] = p;
            p.x = l0; p.y = l1; *(__nv_bfloat162*)&sWl[r0 * AP + cb] = p;
            split2(w10, h0, l0); split2(w11, h1, l1);
            p.x = h0; p.y = h1; *(__nv_bfloat162*)&sWh[(r0 + 8) * AP + cb] = p;
            p.x = l0; p.y = l1; *(__nv_bfloat162*)&sWl[(r0 + 8) * AP + cb] = p;
        }
        __syncthreads();

        // O += W V   (A = W [q][s], B = V^T [d][s]; 3-term split)
        #pragma unroll
        for (int ks = 0; ks < 4; ks++) {
            int kk = ks * 16 + tq * 2;
            uint32_t ah0 = *(const uint32_t*)&sWh[r0 * AP + kk];
            uint32_t ah1 = *(const uint32_t*)&sWh[(r0 + 8) * AP + kk];
            uint32_t ah2 = *(const uint32_t*)&sWh[r0 * AP + kk + 8];
            uint32_t ah3 = *(const uint32_t*)&sWh[(r0 + 8) * AP + kk + 8];
            uint32_t al0 = *(const uint32_t*)&sWl[r0 * AP + kk];
            uint32_t al1 = *(const uint32_t*)&sWl[(r0 + 8) * AP + kk];
            uint32_t al2 = *(const uint32_t*)&sWl[r0 * AP + kk + 8];
            uint32_t al3 = *(const uint32_t*)&sWl[(r0 + 8) * AP + kk + 8];
            #pragma unroll
            for (int nb = 0; nb < 4; nb++) {
                int n = wn * 32 + nb * 8 + g;
                uint32_t bh0 = *(const uint32_t*)&sKh[n * AP + kk];
                uint32_t bh1 = *(const uint32_t*)&sKh[n * AP + kk + 8];
                uint32_t bl0 = *(const uint32_t*)&sKl[n * AP + kk];
                uint32_t bl1 = *(const uint32_t*)&sKl[n * AP + kk + 8];
                mma_bf16(accO[nb], ah0, ah1, ah2, ah3, bh0, bh1);
                mma_bf16(accO[nb], ah0, ah1, ah2, ah3, bl0, bl1);
                mma_bf16(accO[nb], al0, al1, al2, al3, bh0, bh1);
            }
        }
    }

    // Row-sum reduction: lanes within each quad hold disjoint cols of same rows
    sp0 += __shfl_xor_sync(0xffffffffu, sp0, 1);
    sp0 += __shfl_xor_sync(0xffffffffu, sp0, 2);
    sp1 += __shfl_xor_sync(0xffffffffu, sp1, 1);
    sp1 += __shfl_xor_sync(0xffffffffu, sp1, 2);
    if (tq == 0) {
        rsum[wn * 64 + r0]     = sp0;
        rsum[wn * 64 + r0 + 8] = sp1;
    }
    __syncthreads();

    float sink = tanhf(sink_sc[h]) + 1e-6f;
    float a0 = 1.f / (rsum[r0]     + rsum[64 + r0]     + sink + 1e-6f);
    float a1 = 1.f / (rsum[r0 + 8] + rsum[64 + r0 + 8] + sink + 1e-6f);

    #pragma unroll
    for (int nb = 0; nb < 4; nb++) {
        int cb = wn * 32 + nb * 8 + tq * 2;
        float vn0 = v_nulls[h * 64 + cb];
        float vn1 = v_nulls[h * 64 + cb + 1];
        *(float2*)(g_ctxh + (size_t)h * 65536 + (size_t)(t0 + r0) * 64 + cb) =
            make_float2((accO[nb][0] + sink * vn0) * a0,
                        (accO[nb][1] + sink * vn1) * a0);
        *(float2*)(g_ctxh + (size_t)h * 65536 + (size_t)(t0 + r0 + 8) * 64 + cb) =
            make_float2((accO[nb][2] + sink * vn0) * a1,
                        (accO[nb][3] + sink * vn1) * a1);
    }
}

// ---------------------------------------------------------------------------
// Launch
// ---------------------------------------------------------------------------
extern "C" void kernel_launch(void* const* d_in, const int* in_sizes, int n_in,
                              void* d_out, int out_size) {
    const float* X     = (const float*)d_in[0];
    const float* Wq    = (const float*)d_in[1];
    const float* bq    = (const float*)d_in[2];
    const float* Wk    = (const float*)d_in[3];
    const float* bk    = (const float*)d_in[4];
    const float* Wv    = (const float*)d_in[5];
    const float* bv    = (const float*)d_in[6];
    const float* sinkp = (const float*)d_in[7];
    const float* vnull = (const float*)d_in[8];
    const float* Wo    = (const float*)d_in[9];
    const float* bo    = (const float*)d_in[10];
    float* out = (float*)d_out;

    cudaFuncSetAttribute(attn_mma_kernel,
                         cudaFuncAttributeMaxDynamicSharedMemorySize, SMEM_ATTN2);

    rope_table_kernel<<<32, 1024>>>();

    // Operand split/convert for tensor-core GEMMs
    convert_x_kernel<<<(1024 * 1024) / 256, 256>>>(X);
    tconv_kernel<<<dim3(128, 32), dim3(32, 32)>>>(Wq, 1024, 4096, 0);
    tconv_kernel<<<dim3(32, 32),  dim3(32, 32)>>>(Wk, 1024, 1024, 1);
    tconv_kernel<<<dim3(128, 32), dim3(32, 32)>>>(Wv, 1024, 4096, 2);
    tconv_kernel<<<dim3(32, 32),  dim3(32, 32)>>>(Wo, 1024, 1024, 3);

    // Fused QKV projections on tensor cores
    qkv_mma_kernel<<<576, 256>>>(bq, bk, bv);

    // RoPE (in place); K pass also produces per-key denominators
    rope_apply_kernel<<<(T_SEQ * HTOT) / 8, 256>>>(0);
    rope_apply_kernel<<<(T_SEQ * NHEAD) / 8, 256>>>(1);

    // Attention on tensor cores
    attn_mma_kernel<<<dim3(16, 64), 256, SMEM_ATTN2>>>(sinkp, vnull);

    // Branch-average + split, then output projection on tensor cores
    avg_convert_kernel<<<(T_SEQ * DMODEL) / 256, 256>>>();
    out_mma_kernel<<<dim3(8, 8), 256>>>(bo, out);
}